// round 10
// baseline (speedup 1.0000x reference)
#include <cuda_runtime.h>
#include <math_constants.h>

// RMAC: x [64,512,32,32] fp32 -> out [64,512,1,1]
// Row/col ranges (H=W=32, L=3): R0=[0,32) R1=[0,21) R2=[11,32) R3=[0,16) R4=[8,24) R5=[16,32)
// 14 regions: (R0,R0) w=2 (global + l=1), 2x2 over {R1,R2}, 3x3 over {R3,R4,R5}.
// out[b,c] = sum_r w_r * M[b,r,c] / (sqrt(SS[b,r]) + 1e-6)
//
// Stage1: warp owns 4 maps; lane = (map, 16B col-group); 32 serial row loads per
// lane folded into 6 row-primitive accumulators (A..F partition rows) -> zero
// shuffles, minimal STS. Stage2: PDL secondary (launch overlaps stage1 tail).

#define NREG 14

__device__ float g_M[64 * NREG * 512];   // [b][r][ch]
__device__ float g_SS[64 * NREG];        // region sums of squares (atomics);
                                         // zero at load, re-zeroed by stage2.

struct __align__(16) SmemT {
    float s2[4][4][6][36];   // [warp][map][range][col] (pad 36)
    float ssq[4][16];        // per-warp region square partial sums
};

__device__ __forceinline__ float4 f4max(float4 a, float4 b) {
    return make_float4(fmaxf(a.x, b.x), fmaxf(a.y, b.y), fmaxf(a.z, b.z), fmaxf(a.w, b.w));
}

// 128 threads = 4 warps = 16 maps per block; grid 2048.
__global__ __launch_bounds__(128, 8) void rmac_stage1(const float* __restrict__ x) {
    __shared__ SmemT sm;
    const int tid  = threadIdx.x;
    const int w    = tid >> 5;
    const int lane = tid & 31;
    const int m    = lane >> 3;      // map within warp (0..3)
    const int c0   = lane & 7;       // 16B column group (cols 4c0..4c0+3)

    const int wid0 = blockIdx.x * 16;            // first map of block
    const int widw = wid0 + (w << 2);            // first map of warp

    const float4* __restrict__ p =
        (const float4*)x + (size_t)(widw + m) * 256 + c0;

    const float NI = -CUDART_INF_F;
    float4 A = make_float4(NI, NI, NI, NI), B = A, C = A, D = A, E = A, F = A;

    // rows partitioned: A=[0,8) B=[8,11) C=[11,16) D=[16,21) E=[21,24) F=[24,32)
#pragma unroll
    for (int k = 0; k < 32; ++k) {
        float4 v = p[k * 8];
        if (k < 8)       A = f4max(A, v);
        else if (k < 11) B = f4max(B, v);
        else if (k < 16) C = f4max(C, v);
        else if (k < 21) D = f4max(D, v);
        else if (k < 24) E = f4max(E, v);
        else             F = f4max(F, v);
    }

    // rebuild the 6 row-range maxes (11 f4max)
    float4 R3 = f4max(f4max(A, B), C);        // [0,16)
    float4 R1 = f4max(R3, D);                 // [0,21)
    float4 EF = f4max(E, F);
    float4 R5 = f4max(D, EF);                 // [16,32)
    float4 R2 = f4max(C, R5);                 // [11,32)
    float4 R0 = f4max(R1, EF);                // [0,32)
    float4 R4 = f4max(f4max(B, C), f4max(D, E)); // [8,24)

    *(float4*)&sm.s2[w][m][0][c0 << 2] = R0;
    *(float4*)&sm.s2[w][m][1][c0 << 2] = R1;
    *(float4*)&sm.s2[w][m][2][c0 << 2] = R2;
    *(float4*)&sm.s2[w][m][3][c0 << 2] = R3;
    *(float4*)&sm.s2[w][m][4][c0 << 2] = R4;
    *(float4*)&sm.s2[w][m][5][c0 << 2] = R5;
    __syncwarp();

    // epilogue: lanes 0..13 each own one region, serve the warp's 4 maps
    if (lane < NREG) {
        int R, Cc;
        if (lane == 0)     { R = 0; Cc = 0; }
        else if (lane < 5) { R = 1 + ((lane - 1) >> 1); Cc = 1 + ((lane - 1) & 1); }
        else               { int t = lane - 5; R = 3 + t / 3; Cc = 3 + t % 3; }
        const int cs = (Cc == 2) ? 11 : (Cc == 4) ? 8 : (Cc == 5) ? 16 : 0;
        const int ce = (Cc == 1) ? 21 : (Cc == 3) ? 16 : (Cc == 4) ? 24 : 32;

        float sq = 0.0f;
#pragma unroll
        for (int mm_ = 0; mm_ < 4; ++mm_) {
            float mx = -CUDART_INF_F;
            for (int j = cs; j < ce; ++j)
                mx = fmaxf(mx, sm.s2[w][mm_][R][j]);
            const int wid = widw + mm_;
            g_M[((wid >> 9) * NREG + lane) * 512 + (wid & 511)] = mx;
            sq += mx * mx;
        }
        sm.ssq[w][lane] = sq;
    }
    __syncthreads();

    if (tid < NREG) {    // all 16 maps share one batch: wid0 multiple of 16
        const int b = wid0 >> 9;
        float t = sm.ssq[0][tid] + sm.ssq[1][tid] + sm.ssq[2][tid] + sm.ssq[3][tid];
        atomicAdd(&g_SS[b * NREG + tid], t);
    }

    asm volatile("griddepcontrol.launch_dependents;");
}

// PDL secondary: scheduled while stage1 drains; HW-waits for grid completion.
__global__ __launch_bounds__(256) void rmac_stage2(float* __restrict__ out) {
    const int b   = blockIdx.x >> 1;
    const int ch  = ((blockIdx.x & 1) << 8) + threadIdx.x;
    const int tid = threadIdx.x;

    __shared__ float s_inv[NREG];

    asm volatile("griddepcontrol.wait;" ::: "memory");

    if (tid < NREG)
        s_inv[tid] = 1.0f / (sqrtf(g_SS[b * NREG + tid]) + 1e-6f);
    __syncthreads();
    if (tid < NREG)                   // restore zeros for next graph replay
        g_SS[b * NREG + tid] = 0.0f;

    const float* __restrict__ base = g_M + b * NREG * 512 + ch;
    float acc = 2.0f * base[0] * s_inv[0];     // (R0,R0) weight 2
#pragma unroll
    for (int r = 1; r < NREG; ++r)
        acc += base[r * 512] * s_inv[r];
    out[b * 512 + ch] = acc;
}

extern "C" void kernel_launch(void* const* d_in, const int* in_sizes, int n_in,
                              void* d_out, int out_size) {
    const float* x = (const float*)d_in[0];
    float* out = (float*)d_out;

    rmac_stage1<<<2048, 128>>>(x);   // 4 warps x 4 maps per block

    cudaLaunchConfig_t cfg = {};
    cfg.gridDim  = dim3(128, 1, 1);
    cfg.blockDim = dim3(256, 1, 1);
    cfg.dynamicSmemBytes = 0;
    cfg.stream = 0;
    cudaLaunchAttribute attr[1];
    attr[0].id = cudaLaunchAttributeProgrammaticStreamSerialization;
    attr[0].val.programmaticStreamSerializationAllowed = 1;
    cfg.attrs = attr;
    cfg.numAttrs = 1;
    cudaLaunchKernelEx(&cfg, rmac_stage2, out);
}

// round 11
// speedup vs baseline: 1.0077x; 1.0077x over previous
#include <cuda_runtime.h>
#include <math_constants.h>

// RMAC: x [64,512,32,32] fp32 -> out [64,512,1,1] — single kernel, fence-free
// last-tickets epilogue (release-atomic ordering, L2-only epilogue reads; no
// membar.gpu -> no per-block CCTL.IVALL L1 flush).
//
// Row/col ranges (H=W=32, L=3): R0=[0,32) R1=[0,21) R2=[11,32) R3=[0,16) R4=[8,24) R5=[16,32)
// 14 regions: (R0,R0) w=2 (global + l=1), 2x2 over {R1,R2}, 3x3 over {R3,R4,R5}.
// out[b,c] = sum_r w_r * M[b,r,c] / (sqrt(SS[b,r]) + 1e-6)

#define NREG 14
#define NBLK 8192
#define NEPI 256     // last 256 tickets run the epilogue (one 128-ch slice each)

__device__ float g_M[64 * NREG * 512];   // [b][r][ch]
__device__ float g_SS[64 * NREG];        // region sums of squares (atomics)
__device__ unsigned int g_c1 = 0;        // completion tickets
__device__ unsigned int g_c2 = 0;        // epilogue arrivals

struct __align__(16) SmemT {
    float s2[4][6][36];    // [warp][range][col] (pad 36)
    float ssq[4][16];      // per-warp region squares
    float s_inv[16];
    unsigned int ticket;
};

__device__ __forceinline__ float4 f4max(float4 a, float4 b) {
    return make_float4(fmaxf(a.x, b.x), fmaxf(a.y, b.y), fmaxf(a.z, b.z), fmaxf(a.w, b.w));
}
__device__ __forceinline__ float4 shflx4(float4 v, int m) {
    float4 r;
    r.x = __shfl_xor_sync(0xffffffffu, v.x, m);
    r.y = __shfl_xor_sync(0xffffffffu, v.y, m);
    r.z = __shfl_xor_sync(0xffffffffu, v.z, m);
    r.w = __shfl_xor_sync(0xffffffffu, v.w, m);
    return r;
}
__device__ __forceinline__ unsigned int atom_add_release_gpu(unsigned int* p, unsigned int v) {
    unsigned int old;
    asm volatile("atom.add.release.gpu.global.u32 %0, [%1], %2;"
                 : "=r"(old) : "l"(p), "r"(v) : "memory");
    return old;
}
__device__ __forceinline__ unsigned int ld_acquire_gpu(const unsigned int* p) {
    unsigned int v;
    asm volatile("ld.acquire.gpu.global.u32 %0, [%1];" : "=r"(v) : "l"(p) : "memory");
    return v;
}

// Warp per (b,c) map. Lane l: q = l>>3 (row phase), c0 = l&7 (4-col group).
// float4 k covers row 4k+q, cols 4c0..4c0+3. 8x LDG.128 fully coalesced.
__global__ __launch_bounds__(128, 8) void rmac_fused(const float* __restrict__ x,
                                                     float* __restrict__ out) {
    __shared__ SmemT sm;
    const int tid  = threadIdx.x;
    const int w    = tid >> 5;
    const int lane = tid & 31;
    const int wid  = blockIdx.x * 4 + w;      // (b,c) map index
    const int q    = lane >> 3;
    const int c0   = lane & 7;

    // ---------------- stage 1 (identical to measured-best R7 body) -------------
    const float4* __restrict__ p = (const float4*)x + (size_t)wid * 256 + lane;

    float4 v0 = p[0],   v1 = p[32],  v2 = p[64],  v3 = p[96];
    float4 v4 = p[128], v5 = p[160], v6 = p[192], v7 = p[224];

    float4 pc = f4max(v2, v3);                 // rows [8,16)
    float4 pd = f4max(v4, v5);                 // rows [16,24)
    float4 g3 = f4max(f4max(v0, v1), pc);      // rows [0,16)
    float4 g5 = f4max(pd, f4max(v6, v7));      // rows [16,32)
    float4 pb = (q == 3) ? pc : v3;            // rows [11,16): row 11 = k2,q3
    float4 pa = (q == 0) ? pd : v4;            // rows [16,21): row 20 = k5,q0

    float4 m0 = f4max(g3, g5);   // [0,32)
    float4 m1 = f4max(g3, pa);   // [0,21)
    float4 m2 = f4max(pb, g5);   // [11,32)
    float4 m3 = g3;              // [0,16)
    float4 m4 = f4max(pc, pd);   // [8,24)
    float4 m5 = g5;              // [16,32)

    m0 = f4max(m0, shflx4(m0, 8)); m0 = f4max(m0, shflx4(m0, 16));
    m1 = f4max(m1, shflx4(m1, 8)); m1 = f4max(m1, shflx4(m1, 16));
    m2 = f4max(m2, shflx4(m2, 8)); m2 = f4max(m2, shflx4(m2, 16));
    m3 = f4max(m3, shflx4(m3, 8)); m3 = f4max(m3, shflx4(m3, 16));
    m4 = f4max(m4, shflx4(m4, 8)); m4 = f4max(m4, shflx4(m4, 16));
    m5 = f4max(m5, shflx4(m5, 8)); m5 = f4max(m5, shflx4(m5, 16));

    if (q == 0) {   // lanes 0..7 publish col maxes (c0 == lane)
        *(float4*)&sm.s2[w][0][c0 << 2] = m0;
        *(float4*)&sm.s2[w][1][c0 << 2] = m1;
        *(float4*)&sm.s2[w][2][c0 << 2] = m2;
        *(float4*)&sm.s2[w][3][c0 << 2] = m3;
        *(float4*)&sm.s2[w][4][c0 << 2] = m4;
        *(float4*)&sm.s2[w][5][c0 << 2] = m5;
    }
    __syncwarp();

    if (lane < NREG) {
        int R, Cc;
        if (lane == 0)     { R = 0; Cc = 0; }
        else if (lane < 5) { R = 1 + ((lane - 1) >> 1); Cc = 1 + ((lane - 1) & 1); }
        else               { int t = lane - 5; R = 3 + t / 3; Cc = 3 + t % 3; }
        const int cs = (Cc == 2) ? 11 : (Cc == 4) ? 8 : (Cc == 5) ? 16 : 0;
        const int ce = (Cc == 1) ? 21 : (Cc == 3) ? 16 : (Cc == 4) ? 24 : 32;
        float mm = -CUDART_INF_F;
        for (int j = cs; j < ce; ++j)
            mm = fmaxf(mm, sm.s2[w][R][j]);
        const int b = wid >> 9, ch = wid & 511;
        g_M[(b * NREG + lane) * 512 + ch] = mm;
        sm.ssq[w][lane] = mm * mm;
    }
    __syncthreads();

    if (tid < NREG) {   // one atomic per (block, region); 128 blocks per batch
        const int b = blockIdx.x >> 7;
        float t = sm.ssq[0][tid] + sm.ssq[1][tid] + sm.ssq[2][tid] + sm.ssq[3][tid];
        atomicAdd(&g_SS[b * NREG + tid], t);
    }
    __syncthreads();   // all stores/atomics issued before the release ticket

    // ---------------- ticket (release: orders prior STG/RED, no L1 flush) ------
    if (tid == 0) sm.ticket = atom_add_release_gpu(&g_c1, 1u);
    __syncthreads();
    const unsigned int ticket = sm.ticket;

    if (ticket < (unsigned)(NBLK - NEPI)) return;   // early finishers exit

    // ---------------- epilogue: short spin, L2-only reads ----------------------
    if (tid == 0) {
        while (ld_acquire_gpu(&g_c1) < (unsigned)NBLK) __nanosleep(64);
    }
    __syncthreads();

    const int s  = (int)(ticket - (NBLK - NEPI));   // slice 0..255
    const int b  = s >> 2;
    const int ch = ((s & 3) << 7) + tid;            // 128 threads -> 128 channels

    if (tid < NREG)
        sm.s_inv[tid] = 1.0f / (sqrtf(__ldcg(&g_SS[b * NREG + tid])) + 1e-6f);
    __syncthreads();

    const float* __restrict__ base = g_M + b * NREG * 512 + ch;
    float acc = 2.0f * __ldcg(base) * sm.s_inv[0];     // (R0,R0) weight 2
#pragma unroll
    for (int r = 1; r < NREG; ++r)
        acc += __ldcg(base + r * 512) * sm.s_inv[r];
    out[b * 512 + ch] = acc;

    // ---------------- finisher: reset state for next graph replay --------------
    __syncthreads();
    if (tid == 0) sm.ticket = (atom_add_release_gpu(&g_c2, 1u) == (unsigned)(NEPI - 1));
    __syncthreads();
    if (sm.ticket) {   // last epilogue block: everyone has read g_SS already
        for (int i = tid; i < 64 * NREG; i += 128) g_SS[i] = 0.0f;
        __syncthreads();
        if (tid == 0) { g_c2 = 0u; g_c1 = 0u; }
    }
}

extern "C" void kernel_launch(void* const* d_in, const int* in_sizes, int n_in,
                              void* d_out, int out_size) {
    const float* x = (const float*)d_in[0];
    float* out = (float*)d_out;
    rmac_fused<<<NBLK, 128>>>(x, out);
}

// round 12
// speedup vs baseline: 1.0894x; 1.0811x over previous
#include <cuda_runtime.h>
#include <math_constants.h>

// RMAC: x [64,512,32,32] fp32 -> out [64,512,1,1] — single kernel.
// Fusion v4: static last-blocks epilogue + no-return release-RED completion
// counter (no returning single-address atomic anywhere in the main stream —
// that ATOMG return stall was the R8/R11 stream-throttle suspect).
//
// Row/col ranges (H=W=32, L=3): R0=[0,32) R1=[0,21) R2=[11,32) R3=[0,16) R4=[8,24) R5=[16,32)
// 14 regions: (R0,R0) w=2 (global + l=1), 2x2 over {R1,R2}, 3x3 over {R3,R4,R5}.
// out[b,c] = sum_r w_r * M[b,r,c] / (sqrt(SS[b,r]) + 1e-6)

#define NREG 14
#define NBLK 8192
#define NEPI 256     // blocks NBLK-NEPI..NBLK-1 run the epilogue (scheduled last)

__device__ float g_M[64 * NREG * 512];   // [b][r][ch]
__device__ float g_SS[64 * NREG];        // region sums of squares (RED atomics)
__device__ unsigned int g_c1 = 0;        // completion count (RED, no return)
__device__ unsigned int g_c2 = 0;        // epilogue arrivals

struct __align__(16) SmemT {
    float s2[4][6][36];    // [warp][range][col] (pad 36)
    float ssq[4][16];      // per-warp region squares
    float s_inv[16];
    int last;
};

__device__ __forceinline__ float4 f4max(float4 a, float4 b) {
    return make_float4(fmaxf(a.x, b.x), fmaxf(a.y, b.y), fmaxf(a.z, b.z), fmaxf(a.w, b.w));
}
__device__ __forceinline__ float4 shflx4(float4 v, int m) {
    float4 r;
    r.x = __shfl_xor_sync(0xffffffffu, v.x, m);
    r.y = __shfl_xor_sync(0xffffffffu, v.y, m);
    r.z = __shfl_xor_sync(0xffffffffu, v.z, m);
    r.w = __shfl_xor_sync(0xffffffffu, v.w, m);
    return r;
}
__device__ __forceinline__ void red_add_release_gpu(unsigned int* p, unsigned int v) {
    asm volatile("red.release.gpu.global.add.u32 [%0], %1;" :: "l"(p), "r"(v) : "memory");
}
__device__ __forceinline__ unsigned int ld_acquire_gpu(const unsigned int* p) {
    unsigned int v;
    asm volatile("ld.acquire.gpu.global.u32 %0, [%1];" : "=r"(v) : "l"(p) : "memory");
    return v;
}

// Warp per (b,c) map. Lane l: q = l>>3 (row phase), c0 = l&7 (4-col group).
// float4 k covers row 4k+q, cols 4c0..4c0+3. 8x LDG.128 fully coalesced.
__global__ __launch_bounds__(128, 8) void rmac_fused(const float* __restrict__ x,
                                                     float* __restrict__ out) {
    __shared__ SmemT sm;
    const int tid  = threadIdx.x;
    const int w    = tid >> 5;
    const int lane = tid & 31;
    const int wid  = blockIdx.x * 4 + w;      // (b,c) map index
    const int q    = lane >> 3;
    const int c0   = lane & 7;

    // ---------------- stage 1 (identical to measured-best R7 body) -------------
    const float4* __restrict__ p = (const float4*)x + (size_t)wid * 256 + lane;

    float4 v0 = p[0],   v1 = p[32],  v2 = p[64],  v3 = p[96];
    float4 v4 = p[128], v5 = p[160], v6 = p[192], v7 = p[224];

    float4 pc = f4max(v2, v3);                 // rows [8,16)
    float4 pd = f4max(v4, v5);                 // rows [16,24)
    float4 g3 = f4max(f4max(v0, v1), pc);      // rows [0,16)
    float4 g5 = f4max(pd, f4max(v6, v7));      // rows [16,32)
    float4 pb = (q == 3) ? pc : v3;            // rows [11,16): row 11 = k2,q3
    float4 pa = (q == 0) ? pd : v4;            // rows [16,21): row 20 = k5,q0

    float4 m0 = f4max(g3, g5);   // [0,32)
    float4 m1 = f4max(g3, pa);   // [0,21)
    float4 m2 = f4max(pb, g5);   // [11,32)
    float4 m3 = g3;              // [0,16)
    float4 m4 = f4max(pc, pd);   // [8,24)
    float4 m5 = g5;              // [16,32)

    m0 = f4max(m0, shflx4(m0, 8)); m0 = f4max(m0, shflx4(m0, 16));
    m1 = f4max(m1, shflx4(m1, 8)); m1 = f4max(m1, shflx4(m1, 16));
    m2 = f4max(m2, shflx4(m2, 8)); m2 = f4max(m2, shflx4(m2, 16));
    m3 = f4max(m3, shflx4(m3, 8)); m3 = f4max(m3, shflx4(m3, 16));
    m4 = f4max(m4, shflx4(m4, 8)); m4 = f4max(m4, shflx4(m4, 16));
    m5 = f4max(m5, shflx4(m5, 8)); m5 = f4max(m5, shflx4(m5, 16));

    if (q == 0) {   // lanes 0..7 publish col maxes (c0 == lane)
        *(float4*)&sm.s2[w][0][c0 << 2] = m0;
        *(float4*)&sm.s2[w][1][c0 << 2] = m1;
        *(float4*)&sm.s2[w][2][c0 << 2] = m2;
        *(float4*)&sm.s2[w][3][c0 << 2] = m3;
        *(float4*)&sm.s2[w][4][c0 << 2] = m4;
        *(float4*)&sm.s2[w][5][c0 << 2] = m5;
    }
    __syncwarp();

    if (lane < NREG) {
        int R, Cc;
        if (lane == 0)     { R = 0; Cc = 0; }
        else if (lane < 5) { R = 1 + ((lane - 1) >> 1); Cc = 1 + ((lane - 1) & 1); }
        else               { int t = lane - 5; R = 3 + t / 3; Cc = 3 + t % 3; }
        const int cs = (Cc == 2) ? 11 : (Cc == 4) ? 8 : (Cc == 5) ? 16 : 0;
        const int ce = (Cc == 1) ? 21 : (Cc == 3) ? 16 : (Cc == 4) ? 24 : 32;
        float mm = -CUDART_INF_F;
        for (int j = cs; j < ce; ++j)
            mm = fmaxf(mm, sm.s2[w][R][j]);
        const int b = wid >> 9, ch = wid & 511;
        g_M[(b * NREG + lane) * 512 + ch] = mm;
        sm.ssq[w][lane] = mm * mm;
    }
    __syncthreads();

    if (tid < NREG) {   // return-unused atomicAdd -> RED (no return), 896 addrs
        const int b = blockIdx.x >> 7;
        float t = sm.ssq[0][tid] + sm.ssq[1][tid] + sm.ssq[2][tid] + sm.ssq[3][tid];
        atomicAdd(&g_SS[b * NREG + tid], t);
    }
    __syncthreads();   // all stores/REDs issued before the completion signal

    // ---------------- completion: fire-and-forget release RED ------------------
    if (tid == 0) red_add_release_gpu(&g_c1, 1u);

    if (blockIdx.x < NBLK - NEPI) return;   // non-epilogue blocks exit immediately

    // ---------------- epilogue: last-scheduled 256 blocks ----------------------
    if (tid == 0) {
        while (ld_acquire_gpu(&g_c1) < (unsigned)NBLK) __nanosleep(64);
    }
    __syncthreads();

    const int s  = blockIdx.x - (NBLK - NEPI);      // slice 0..255
    const int b  = s >> 2;
    const int ch = ((s & 3) << 7) + tid;            // 128 threads -> 128 channels

    if (tid < NREG)
        sm.s_inv[tid] = 1.0f / (sqrtf(__ldcg(&g_SS[b * NREG + tid])) + 1e-6f);
    __syncthreads();

    const float* __restrict__ base = g_M + b * NREG * 512 + ch;
    float acc = 2.0f * __ldcg(base) * sm.s_inv[0];     // (R0,R0) weight 2
#pragma unroll
    for (int r = 1; r < NREG; ++r)
        acc += __ldcg(base + r * 512) * sm.s_inv[r];
    out[b * 512 + ch] = acc;

    // ---------------- finisher: reset state for next graph replay --------------
    __syncthreads();
    if (tid == 0) sm.last = (atomicAdd(&g_c2, 1u) == (unsigned)(NEPI - 1));
    __syncthreads();
    if (sm.last) {   // all 256 epilogue blocks have read g_SS by now
        for (int i = tid; i < 64 * NREG; i += 128) g_SS[i] = 0.0f;
        __syncthreads();
        if (tid == 0) { g_c2 = 0u; g_c1 = 0u; }
    }
}

extern "C" void kernel_launch(void* const* d_in, const int* in_sizes, int n_in,
                              void* d_out, int out_size) {
    const float* x = (const float*)d_in[0];
    float* out = (float*)d_out;
    rmac_fused<<<NBLK, 128>>>(x, out);
}

// round 13
// speedup vs baseline: 1.1491x; 1.0548x over previous
#include <cuda_runtime.h>
#include <math_constants.h>

// RMAC: x [64,512,32,32] fp32 -> out [64,512,1,1]
// Row/col ranges (H=W=32, L=3): R0=[0,32) R1=[0,21) R2=[11,32) R3=[0,16) R4=[8,24) R5=[16,32)
// 14 regions: (R0,R0) w=2 (global + l=1), 2x2 over {R1,R2}, 3x3 over {R3,R4,R5}.
// out[b,c] = sum_r w_r * M[b,r,c] / (sqrt(SS[b,r]) + 1e-6)
//
// Two kernels (fusion measured worse 4x). Stage2: PDL secondary with g_M loads
// hoisted ahead of the norm chain so both DRAM round-trips overlap.

#define NREG 14

__device__ float g_M[64 * NREG * 512];   // [b][r][ch]
__device__ float g_SS[64 * NREG];        // region sums of squares (RED atomics);
                                         // zero at load, re-zeroed by stage2.

struct __align__(16) SmemT {
    float s2[4][6][36];    // [warp][range][col] (pad 36)
    float ssq[4][16];      // per-warp region squares
};

__device__ __forceinline__ float4 f4max(float4 a, float4 b) {
    return make_float4(fmaxf(a.x, b.x), fmaxf(a.y, b.y), fmaxf(a.z, b.z), fmaxf(a.w, b.w));
}
__device__ __forceinline__ float4 shflx4(float4 v, int m) {
    float4 r;
    r.x = __shfl_xor_sync(0xffffffffu, v.x, m);
    r.y = __shfl_xor_sync(0xffffffffu, v.y, m);
    r.z = __shfl_xor_sync(0xffffffffu, v.z, m);
    r.w = __shfl_xor_sync(0xffffffffu, v.w, m);
    return r;
}

// Warp per (b,c) map. Lane l: q = l>>3 (row phase), c0 = l&7 (4-col group).
// float4 k covers row 4k+q, cols 4c0..4c0+3. 8x LDG.128 fully coalesced.
__global__ __launch_bounds__(128, 8) void rmac_stage1(const float* __restrict__ x) {
    __shared__ SmemT sm;
    const int tid  = threadIdx.x;
    const int w    = tid >> 5;
    const int lane = tid & 31;
    const int wid  = blockIdx.x * 4 + w;      // (b,c) map index
    const int q    = lane >> 3;
    const int c0   = lane & 7;

    const float4* __restrict__ p = (const float4*)x + (size_t)wid * 256 + lane;

    float4 v0 = p[0],   v1 = p[32],  v2 = p[64],  v3 = p[96];
    float4 v4 = p[128], v5 = p[160], v6 = p[192], v7 = p[224];

    float4 pc = f4max(v2, v3);                 // rows [8,16)
    float4 pd = f4max(v4, v5);                 // rows [16,24)
    float4 g3 = f4max(f4max(v0, v1), pc);      // rows [0,16)
    float4 g5 = f4max(pd, f4max(v6, v7));      // rows [16,32)
    float4 pb = (q == 3) ? pc : v3;            // rows [11,16): row 11 = k2,q3
    float4 pa = (q == 0) ? pd : v4;            // rows [16,21): row 20 = k5,q0

    float4 m0 = f4max(g3, g5);   // [0,32)
    float4 m1 = f4max(g3, pa);   // [0,21)
    float4 m2 = f4max(pb, g5);   // [11,32)
    float4 m3 = g3;              // [0,16)
    float4 m4 = f4max(pc, pd);   // [8,24)
    float4 m5 = g5;              // [16,32)

    // Butterfly over row-phase q (lane bits 3,4): full column maxes in all lanes.
    m0 = f4max(m0, shflx4(m0, 8)); m0 = f4max(m0, shflx4(m0, 16));
    m1 = f4max(m1, shflx4(m1, 8)); m1 = f4max(m1, shflx4(m1, 16));
    m2 = f4max(m2, shflx4(m2, 8)); m2 = f4max(m2, shflx4(m2, 16));
    m3 = f4max(m3, shflx4(m3, 8)); m3 = f4max(m3, shflx4(m3, 16));
    m4 = f4max(m4, shflx4(m4, 8)); m4 = f4max(m4, shflx4(m4, 16));
    m5 = f4max(m5, shflx4(m5, 8)); m5 = f4max(m5, shflx4(m5, 16));

    if (q == 0) {   // lanes 0..7 publish col maxes (c0 == lane)
        *(float4*)&sm.s2[w][0][c0 << 2] = m0;
        *(float4*)&sm.s2[w][1][c0 << 2] = m1;
        *(float4*)&sm.s2[w][2][c0 << 2] = m2;
        *(float4*)&sm.s2[w][3][c0 << 2] = m3;
        *(float4*)&sm.s2[w][4][c0 << 2] = m4;
        *(float4*)&sm.s2[w][5][c0 << 2] = m5;
    }
    __syncwarp();

    if (lane < NREG) {
        int R, Cc;
        if (lane == 0)     { R = 0; Cc = 0; }
        else if (lane < 5) { R = 1 + ((lane - 1) >> 1); Cc = 1 + ((lane - 1) & 1); }
        else               { int t = lane - 5; R = 3 + t / 3; Cc = 3 + t % 3; }
        const int cs = (Cc == 2) ? 11 : (Cc == 4) ? 8 : (Cc == 5) ? 16 : 0;
        const int ce = (Cc == 1) ? 21 : (Cc == 3) ? 16 : (Cc == 4) ? 24 : 32;
        float mm = -CUDART_INF_F;
        for (int j = cs; j < ce; ++j)
            mm = fmaxf(mm, sm.s2[w][R][j]);
        const int b = wid >> 9, ch = wid & 511;
        g_M[(b * NREG + lane) * 512 + ch] = mm;
        sm.ssq[w][lane] = mm * mm;
    }
    __syncthreads();

    if (tid < NREG) {   // return-unused -> RED (no-return), 896 spread addresses
        const int b = blockIdx.x >> 7;
        float t = sm.ssq[0][tid] + sm.ssq[1][tid] + sm.ssq[2][tid] + sm.ssq[3][tid];
        atomicAdd(&g_SS[b * NREG + tid], t);
    }

    asm volatile("griddepcontrol.launch_dependents;");
}

// PDL secondary: scheduled while stage1 drains; HW-waits for grid completion.
// g_M loads hoisted ahead of the g_SS/sqrt chain so the two DRAM round-trips
// overlap instead of serializing across the __syncthreads broadcast.
__global__ __launch_bounds__(256) void rmac_stage2(float* __restrict__ out) {
    const int b   = blockIdx.x >> 1;
    const int ch  = ((blockIdx.x & 1) << 8) + threadIdx.x;
    const int tid = threadIdx.x;

    __shared__ float s_inv[NREG];

    asm volatile("griddepcontrol.wait;" ::: "memory");

    // issue all 14 independent g_M loads first (overlap with norm chain below)
    const float* __restrict__ base = g_M + b * NREG * 512 + ch;
    float v[NREG];
#pragma unroll
    for (int r = 0; r < NREG; ++r)
        v[r] = __ldcg(base + r * 512);

    if (tid < NREG)
        s_inv[tid] = 1.0f / (sqrtf(__ldcg(&g_SS[b * NREG + tid])) + 1e-6f);
    __syncthreads();
    if (tid < NREG)                  // re-zero off the critical path (own value
        g_SS[b * NREG + tid] = 0.0f; // already consumed above)

    float acc = 2.0f * v[0] * s_inv[0];     // (R0,R0) weight 2
#pragma unroll
    for (int r = 1; r < NREG; ++r)
        acc += v[r] * s_inv[r];
    out[b * 512 + ch] = acc;
}

extern "C" void kernel_launch(void* const* d_in, const int* in_sizes, int n_in,
                              void* d_out, int out_size) {
    const float* x = (const float*)d_in[0];
    float* out = (float*)d_out;

    rmac_stage1<<<8192, 128>>>(x);

    cudaLaunchConfig_t cfg = {};
    cfg.gridDim  = dim3(128, 1, 1);
    cfg.blockDim = dim3(256, 1, 1);
    cfg.dynamicSmemBytes = 0;
    cfg.stream = 0;
    cudaLaunchAttribute attr[1];
    attr[0].id = cudaLaunchAttributeProgrammaticStreamSerialization;
    attr[0].val.programmaticStreamSerializationAllowed = 1;
    cfg.attrs = attr;
    cfg.numAttrs = 1;
    cudaLaunchKernelEx(&cfg, rmac_stage2, out);
}

// round 14
// speedup vs baseline: 1.1504x; 1.0011x over previous
#include <cuda_runtime.h>
#include <math_constants.h>

// RMAC: x [64,512,32,32] fp32 -> out [64,512,1,1]
// Row/col ranges (H=W=32, L=3): R0=[0,32) R1=[0,21) R2=[11,32) R3=[0,16) R4=[8,24) R5=[16,32)
// 14 regions: (R0,R0) w=2 (global + l=1), 2x2 over {R1,R2}, 3x3 over {R3,R4,R5}.
// out[b,c] = sum_r w_r * M[b,r,c] / (sqrt(SS[b,r]) + 1e-6)
//
// Two kernels. Stage1 reads x with __ldcs (evict-first: x is stream-once) so
// g_M/g_SS stay L2-resident for stage2. Stage2 is a PDL secondary.

#define NREG 14

__device__ float g_M[64 * NREG * 512];   // [b][r][ch]
__device__ float g_SS[64 * NREG];        // region sums of squares (RED atomics);
                                         // zero at load, re-zeroed by stage2.

struct __align__(16) SmemT {
    float s2[4][6][36];    // [warp][range][col] (pad 36)
    float ssq[4][16];      // per-warp region squares
};

__device__ __forceinline__ float4 f4max(float4 a, float4 b) {
    return make_float4(fmaxf(a.x, b.x), fmaxf(a.y, b.y), fmaxf(a.z, b.z), fmaxf(a.w, b.w));
}
__device__ __forceinline__ float4 shflx4(float4 v, int m) {
    float4 r;
    r.x = __shfl_xor_sync(0xffffffffu, v.x, m);
    r.y = __shfl_xor_sync(0xffffffffu, v.y, m);
    r.z = __shfl_xor_sync(0xffffffffu, v.z, m);
    r.w = __shfl_xor_sync(0xffffffffu, v.w, m);
    return r;
}

// Warp per (b,c) map. Lane l: q = l>>3 (row phase), c0 = l&7 (4-col group).
// float4 k covers row 4k+q, cols 4c0..4c0+3. 8x LDG.128 fully coalesced.
__global__ __launch_bounds__(128, 8) void rmac_stage1(const float* __restrict__ x) {
    __shared__ SmemT sm;
    const int tid  = threadIdx.x;
    const int w    = tid >> 5;
    const int lane = tid & 31;
    const int wid  = blockIdx.x * 4 + w;      // (b,c) map index
    const int q    = lane >> 3;
    const int c0   = lane & 7;

    const float4* __restrict__ p = (const float4*)x + (size_t)wid * 256 + lane;

    float4 v0 = __ldcs(p +   0), v1 = __ldcs(p +  32);
    float4 v2 = __ldcs(p +  64), v3 = __ldcs(p +  96);
    float4 v4 = __ldcs(p + 128), v5 = __ldcs(p + 160);
    float4 v6 = __ldcs(p + 192), v7 = __ldcs(p + 224);

    float4 pc = f4max(v2, v3);                 // rows [8,16)
    float4 pd = f4max(v4, v5);                 // rows [16,24)
    float4 g3 = f4max(f4max(v0, v1), pc);      // rows [0,16)
    float4 g5 = f4max(pd, f4max(v6, v7));      // rows [16,32)
    float4 pb = (q == 3) ? pc : v3;            // rows [11,16): row 11 = k2,q3
    float4 pa = (q == 0) ? pd : v4;            // rows [16,21): row 20 = k5,q0

    float4 m0 = f4max(g3, g5);   // [0,32)
    float4 m1 = f4max(g3, pa);   // [0,21)
    float4 m2 = f4max(pb, g5);   // [11,32)
    float4 m3 = g3;              // [0,16)
    float4 m4 = f4max(pc, pd);   // [8,24)
    float4 m5 = g5;              // [16,32)

    // Butterfly over row-phase q (lane bits 3,4): full column maxes in all lanes.
    m0 = f4max(m0, shflx4(m0, 8)); m0 = f4max(m0, shflx4(m0, 16));
    m1 = f4max(m1, shflx4(m1, 8)); m1 = f4max(m1, shflx4(m1, 16));
    m2 = f4max(m2, shflx4(m2, 8)); m2 = f4max(m2, shflx4(m2, 16));
    m3 = f4max(m3, shflx4(m3, 8)); m3 = f4max(m3, shflx4(m3, 16));
    m4 = f4max(m4, shflx4(m4, 8)); m4 = f4max(m4, shflx4(m4, 16));
    m5 = f4max(m5, shflx4(m5, 8)); m5 = f4max(m5, shflx4(m5, 16));

    if (q == 0) {   // lanes 0..7 publish col maxes (c0 == lane)
        *(float4*)&sm.s2[w][0][c0 << 2] = m0;
        *(float4*)&sm.s2[w][1][c0 << 2] = m1;
        *(float4*)&sm.s2[w][2][c0 << 2] = m2;
        *(float4*)&sm.s2[w][3][c0 << 2] = m3;
        *(float4*)&sm.s2[w][4][c0 << 2] = m4;
        *(float4*)&sm.s2[w][5][c0 << 2] = m5;
    }
    __syncwarp();

    if (lane < NREG) {
        int R, Cc;
        if (lane == 0)     { R = 0; Cc = 0; }
        else if (lane < 5) { R = 1 + ((lane - 1) >> 1); Cc = 1 + ((lane - 1) & 1); }
        else               { int t = lane - 5; R = 3 + t / 3; Cc = 3 + t % 3; }
        const int cs = (Cc == 2) ? 11 : (Cc == 4) ? 8 : (Cc == 5) ? 16 : 0;
        const int ce = (Cc == 1) ? 21 : (Cc == 3) ? 16 : (Cc == 4) ? 24 : 32;
        float mm = -CUDART_INF_F;
        for (int j = cs; j < ce; ++j)
            mm = fmaxf(mm, sm.s2[w][R][j]);
        const int b = wid >> 9, ch = wid & 511;
        g_M[(b * NREG + lane) * 512 + ch] = mm;
        sm.ssq[w][lane] = mm * mm;
    }
    __syncthreads();

    if (tid < NREG) {   // return-unused -> RED (no-return), 896 spread addresses
        const int b = blockIdx.x >> 7;
        float t = sm.ssq[0][tid] + sm.ssq[1][tid] + sm.ssq[2][tid] + sm.ssq[3][tid];
        atomicAdd(&g_SS[b * NREG + tid], t);
    }

    asm volatile("griddepcontrol.launch_dependents;");
}

// PDL secondary: scheduled while stage1 drains; HW-waits for grid completion.
// g_M/g_SS should be L2-hot (stage1's x reads were evict-first).
__global__ __launch_bounds__(256) void rmac_stage2(float* __restrict__ out) {
    const int b   = blockIdx.x >> 1;
    const int ch  = ((blockIdx.x & 1) << 8) + threadIdx.x;
    const int tid = threadIdx.x;

    __shared__ float s_inv[NREG];

    asm volatile("griddepcontrol.wait;" ::: "memory");

    // issue all 14 independent g_M loads first (overlap with norm chain below)
    const float* __restrict__ base = g_M + b * NREG * 512 + ch;
    float v[NREG];
#pragma unroll
    for (int r = 0; r < NREG; ++r)
        v[r] = base[r * 512];

    if (tid < NREG)
        s_inv[tid] = 1.0f / (sqrtf(g_SS[b * NREG + tid]) + 1e-6f);
    __syncthreads();
    if (tid < NREG)                  // re-zero off the critical path
        g_SS[b * NREG + tid] = 0.0f;

    float acc = 2.0f * v[0] * s_inv[0];     // (R0,R0) weight 2
#pragma unroll
    for (int r = 1; r < NREG; ++r)
        acc += v[r] * s_inv[r];
    out[b * 512 + ch] = acc;
}

extern "C" void kernel_launch(void* const* d_in, const int* in_sizes, int n_in,
                              void* d_out, int out_size) {
    const float* x = (const float*)d_in[0];
    float* out = (float*)d_out;

    rmac_stage1<<<8192, 128>>>(x);

    cudaLaunchConfig_t cfg = {};
    cfg.gridDim  = dim3(128, 1, 1);
    cfg.blockDim = dim3(256, 1, 1);
    cfg.dynamicSmemBytes = 0;
    cfg.stream = 0;
    cudaLaunchAttribute attr[1];
    attr[0].id = cudaLaunchAttributeProgrammaticStreamSerialization;
    attr[0].val.programmaticStreamSerializationAllowed = 1;
    cfg.attrs = attr;
    cfg.numAttrs = 1;
    cudaLaunchKernelEx(&cfg, rmac_stage2, out);
}